// round 15
// baseline (speedup 1.0000x reference)
#include <cuda_runtime.h>

// Problem constants
#define B_ 64
#define T_ 4096
#define C_ 8
#define K_ 150
#define TOKW 64                            // tokens per warp (phase 2)
#define WARPS_ 4
#define THREADS_ (WARPS_ * 32)             // 128
#define TOK_PER_BLOCK 256                  // phase-1: 2 tokens/thread
#define BLOCKS_PER_B (T_ / TOK_PER_BLOCK)  // 16
#define GRID_ (B_ * BLOCKS_PER_B)          // 1024

// Scratch accumulators. __device__ globals are zero-initialized at module load;
// finalize_kernel re-zeroes them after use, so every call sees zeros.
__device__ float g_num[B_ * K_ * C_];   // [B,K,C]
__device__ float g_den[B_ * K_];        // [B,K]

__device__ __forceinline__ float ex2f(float x) {
    float y; asm("ex2.approx.f32 %0, %1;" : "=f"(y) : "f"(x)); return y;
}
__device__ __forceinline__ float rcpf(float x) {
    float y; asm("rcp.approx.f32 %0, %1;" : "=f"(y) : "f"(x)); return y;
}

// Fused two-phase kernel (R13: phase 2 split into two k-range passes to cut
// peak live registers -> 6 blocks/SM instead of 4; R12 profile showed
// issue=50.6% with occ=20.7% and NO saturated pipe => latency-hiding bound).
//   softmax(-dist) == softmax(2*x.c - |c|^2): |x|^2 cancels across k.
//   exp(l) == 2^(l*log2e): log2e folded into staged centroids -> one EX2.
// Phase 1 (thread = 2 tokens): private softmax denominators, zero cross-lane ops.
// Phase 2 (warp = 64 tokens; pass A: k=lane+{0,32,64}, pass B: k=lane+{96,128}):
//   recompute exps, scale by smem r, store + register-accumulate, flush per pass.
__global__ void __launch_bounds__(THREADS_, 6)
softkmeans_kernel(const float* __restrict__ x,
                  const float* __restrict__ cent,
                  float* __restrict__ assign_out) {
    __shared__ float  scw[K_ * C_];           // 2*log2e*c      (4.8 KB)
    __shared__ float  sbias[K_];              // -log2e*|c|^2   (0.6 KB)
    __shared__ float4 sx[TOK_PER_BLOCK * 2];  // x tokens       (8 KB)
    __shared__ float  sr[TOK_PER_BLOCK];      // 1/sum_exp      (1 KB)

    const int tid  = threadIdx.x;
    const int warp = tid >> 5;
    const int lane = tid & 31;
    const int b    = blockIdx.x / BLOCKS_PER_B;
    const int blk  = blockIdx.x % BLOCKS_PER_B;
    const float L2E = 1.4426950408889634f;

    // ---- stage centroids (pre-scaled) ----
    for (int k = tid; k < K_; k += THREADS_) {
        float s = 0.0f, tmp[C_];
#pragma unroll
        for (int c = 0; c < C_; c++) {
            tmp[c] = cent[k * C_ + c];
            s = fmaf(tmp[c], tmp[c], s);
        }
#pragma unroll
        for (int c = 0; c < C_; c++) scw[k * C_ + c] = 2.0f * L2E * tmp[c];
        sbias[k] = -L2E * s;
    }

    // ---- stage x: 256 tokens * 32B, coalesced; kept in regs for phase 1 ----
    const float* xg = x + ((size_t)b * T_ + blk * TOK_PER_BLOCK) * C_;
    const float4* xp4 = (const float4*)xg;
    float4 pa0 = xp4[tid * 2], pa1 = xp4[tid * 2 + 1];
    float4 pb0 = xp4[(tid + 128) * 2], pb1 = xp4[(tid + 128) * 2 + 1];
    sx[tid * 2] = pa0;  sx[tid * 2 + 1] = pa1;
    sx[(tid + 128) * 2] = pb0;  sx[(tid + 128) * 2 + 1] = pb1;
    __syncthreads();

    // ---- phase 1: per-thread softmax denominators for 2 tokens ----
    {
        float xa[C_]  = {pa0.x, pa0.y, pa0.z, pa0.w, pa1.x, pa1.y, pa1.z, pa1.w};
        float xbv[C_] = {pb0.x, pb0.y, pb0.z, pb0.w, pb1.x, pb1.y, pb1.z, pb1.w};
        float s0a = 0.0f, s0b = 0.0f, s1a = 0.0f, s1b = 0.0f;
#pragma unroll 4
        for (int k = 0; k < K_; k++) {
            const float* w = &scw[k * C_];     // broadcast LDS, conflict-free
            float bias = sbias[k];
            float l0 = bias, l1 = bias;
#pragma unroll
            for (int c = 0; c < C_; c++) {
                l0 = fmaf(w[c], xa[c], l0);
                l1 = fmaf(w[c], xbv[c], l1);
            }
            if (k & 1) { s0b += ex2f(l0); s1b += ex2f(l1); }
            else       { s0a += ex2f(l0); s1a += ex2f(l1); }
        }
        sr[tid]       = rcpf(s0a + s0b);
        sr[tid + 128] = rcpf(s1a + s1b);
    }
    __syncthreads();

    float* ab = assign_out + ((size_t)b * T_ + blk * TOK_PER_BLOCK + warp * TOKW) * (size_t)K_;
    const float4* s4 = sx + warp * (TOKW * 2);
    const float*  rr = sr + warp * TOKW;

    // ======== phase 2, pass A: slices i=0..2 (k = lane, lane+32, lane+64) ====
    {
        float cwl[3][C_], nl[3];
#pragma unroll
        for (int i = 0; i < 3; i++) {
            int k = lane + 32 * i;
#pragma unroll
            for (int c = 0; c < C_; c++) cwl[i][c] = scw[k * C_ + c];
            nl[i] = sbias[k];
        }
        float num[3][C_], den[3];
#pragma unroll
        for (int i = 0; i < 3; i++) {
            den[i] = 0.0f;
#pragma unroll
            for (int c = 0; c < C_; c++) num[i][c] = 0.0f;
        }

#pragma unroll 2
        for (int tt = 0; tt < TOKW; tt++) {
            float4 x0 = s4[2 * tt];
            float4 x1 = s4[2 * tt + 1];
            float  r  = rr[tt];
            float xv[C_] = {x0.x, x0.y, x0.z, x0.w, x1.x, x1.y, x1.z, x1.w};

            float a[3];
#pragma unroll
            for (int i = 0; i < 3; i++) {
                float l = nl[i];
#pragma unroll
                for (int c = 0; c < C_; c++) l = fmaf(cwl[i][c], xv[c], l);
                a[i] = ex2f(l) * r;
            }
            float* ap = ab + (size_t)tt * K_;
            ap[lane]      = a[0];     // coalesced 128B stores
            ap[lane + 32] = a[1];
            ap[lane + 64] = a[2];
#pragma unroll
            for (int i = 0; i < 3; i++) {
                den[i] += a[i];
#pragma unroll
                for (int c = 0; c < C_; c++) num[i][c] = fmaf(a[i], xv[c], num[i][c]);
            }
        }
#pragma unroll
        for (int i = 0; i < 3; i++) {
            int k = lane + 32 * i;
            atomicAdd(&g_den[b * K_ + k], den[i]);
#pragma unroll
            for (int c = 0; c < C_; c++)
                atomicAdd(&g_num[(b * K_ + k) * C_ + c], num[i][c]);
        }
    }

    // ======== phase 2, pass B: slices i=3,4 (k = lane+96, lane+128) =========
    {
        const bool v4 = (lane + 128) < K_;
        float cwl[2][C_], nl[2];
        {
            int k = lane + 96;
#pragma unroll
            for (int c = 0; c < C_; c++) cwl[0][c] = scw[k * C_ + c];
            nl[0] = sbias[k];
        }
        if (v4) {
            int k = lane + 128;
#pragma unroll
            for (int c = 0; c < C_; c++) cwl[1][c] = scw[k * C_ + c];
            nl[1] = sbias[k];
        } else {
#pragma unroll
            for (int c = 0; c < C_; c++) cwl[1][c] = 0.0f;
            nl[1] = __int_as_float(0xff800000);   // -inf -> ex2 -> 0
        }
        float num[2][C_], den[2];
#pragma unroll
        for (int i = 0; i < 2; i++) {
            den[i] = 0.0f;
#pragma unroll
            for (int c = 0; c < C_; c++) num[i][c] = 0.0f;
        }

#pragma unroll 2
        for (int tt = 0; tt < TOKW; tt++) {
            float4 x0 = s4[2 * tt];
            float4 x1 = s4[2 * tt + 1];
            float  r  = rr[tt];
            float xv[C_] = {x0.x, x0.y, x0.z, x0.w, x1.x, x1.y, x1.z, x1.w};

            float a[2];
#pragma unroll
            for (int i = 0; i < 2; i++) {
                float l = nl[i];
#pragma unroll
                for (int c = 0; c < C_; c++) l = fmaf(cwl[i][c], xv[c], l);
                a[i] = ex2f(l) * r;
            }
            float* ap = ab + (size_t)tt * K_;
            ap[lane + 96] = a[0];
            if (v4) ap[lane + 128] = a[1];
#pragma unroll
            for (int i = 0; i < 2; i++) {
                den[i] += a[i];
#pragma unroll
                for (int c = 0; c < C_; c++) num[i][c] = fmaf(a[i], xv[c], num[i][c]);
            }
        }
        {
            int k = lane + 96;
            atomicAdd(&g_den[b * K_ + k], den[0]);
#pragma unroll
            for (int c = 0; c < C_; c++)
                atomicAdd(&g_num[(b * K_ + k) * C_ + c], num[0][c]);
        }
        if (v4) {
            int k = lane + 128;
            atomicAdd(&g_den[b * K_ + k], den[1]);
#pragma unroll
            for (int c = 0; c < C_; c++)
                atomicAdd(&g_num[(b * K_ + k) * C_ + c], num[1][c]);
        }
    }
}

// Divide, then self-clean the accumulators for the next call.
// 8 consecutive i share one g_den entry and live in the same warp: the LDG of
// den precedes the lane-0 STG of zero in program order, so no race.
__global__ void finalize_kernel(float* __restrict__ pe) {
    int i = blockIdx.x * blockDim.x + threadIdx.x;
    if (i < B_ * K_ * C_) {
        float d = g_den[i >> 3];   // C_ == 8
        float n = g_num[i];
        pe[i] = n / (d + 1e-8f);
        g_num[i] = 0.0f;
        if ((i & 7) == 0) g_den[i >> 3] = 0.0f;
    }
}

// Keeps the 3-launches cadence so the fixed ncu capture slot profiles the main kernel.
__global__ void pad_kernel() {}

extern "C" void kernel_launch(void* const* d_in, const int* in_sizes, int n_in,
                              void* d_out, int out_size) {
    const float* x    = (const float*)d_in[0];   // [B,T,C]
    const float* cent = (const float*)d_in[1];   // [K,C]
    float* out        = (float*)d_out;
    float* pe_out     = out;                               // [B,K,C] (tuple order)
    float* assign_out = out + (size_t)B_ * K_ * C_;        // [B,T,K]

    softkmeans_kernel<<<GRID_, THREADS_>>>(x, cent, assign_out);
    finalize_kernel<<<(B_ * K_ * C_ + 255) / 256, 256>>>(pe_out);
    pad_kernel<<<1, 32>>>();
}

// round 16
// speedup vs baseline: 1.1590x; 1.1590x over previous
#include <cuda_runtime.h>

// Problem constants
#define B_ 64
#define T_ 4096
#define C_ 8
#define K_ 150
#define TOKW 64                            // tokens per warp (phase 2)
#define WARPS_ 4
#define THREADS_ (WARPS_ * 32)             // 128
#define TOK_PER_BLOCK 256                  // phase-1: 2 tokens/thread
#define BLOCKS_PER_B (T_ / TOK_PER_BLOCK)  // 16
#define GRID_ (B_ * BLOCKS_PER_B)          // 1024

// Scratch accumulators. __device__ globals are zero-initialized at module load;
// finalize_kernel re-zeroes them after use, so every call sees zeros.
__device__ float g_num[B_ * K_ * C_];   // [B,K,C]
__device__ float g_den[B_ * K_];        // [B,K]

__device__ __forceinline__ float ex2f(float x) {
    float y; asm("ex2.approx.f32 %0, %1;" : "=f"(y) : "f"(x)); return y;
}
__device__ __forceinline__ float rcpf(float x) {
    float y; asm("rcp.approx.f32 %0, %1;" : "=f"(y) : "f"(x)); return y;
}

// Fused two-phase kernel (R16: single-pass phase 2 like R12 — R13 proved
// occupancy is NOT the binding constraint — plus explicit software pipelining:
// prefetch next token's x/r into regs and unroll 4 so ptxas interleaves the
// 8-deep FMA dot chains of 4 tokens; per-warp duty was ~15%).
//   softmax(-dist) == softmax(2*x.c - |c|^2): |x|^2 cancels across k.
//   exp(l) == 2^(l*log2e): log2e folded into staged centroids -> one EX2.
// Phase 1 (thread = 2 tokens): private softmax denominators, zero cross-lane ops.
// Phase 2 (warp = 64 tokens, lane owns k = lane+32i): recompute exps, scale by
//   smem r, store + register-accumulate, single atomic flush.
__global__ void __launch_bounds__(THREADS_, 4)
softkmeans_kernel(const float* __restrict__ x,
                  const float* __restrict__ cent,
                  float* __restrict__ assign_out) {
    __shared__ float  scw[K_ * C_];           // 2*log2e*c      (4.8 KB)
    __shared__ float  sbias[K_];              // -log2e*|c|^2   (0.6 KB)
    __shared__ float4 sx[TOK_PER_BLOCK * 2];  // x tokens       (8 KB)
    __shared__ float  sr[TOK_PER_BLOCK];      // 1/sum_exp      (1 KB)

    const int tid  = threadIdx.x;
    const int warp = tid >> 5;
    const int lane = tid & 31;
    const int b    = blockIdx.x / BLOCKS_PER_B;
    const int blk  = blockIdx.x % BLOCKS_PER_B;
    const float L2E = 1.4426950408889634f;

    // ---- stage centroids (pre-scaled) ----
    for (int k = tid; k < K_; k += THREADS_) {
        float s = 0.0f, tmp[C_];
#pragma unroll
        for (int c = 0; c < C_; c++) {
            tmp[c] = cent[k * C_ + c];
            s = fmaf(tmp[c], tmp[c], s);
        }
#pragma unroll
        for (int c = 0; c < C_; c++) scw[k * C_ + c] = 2.0f * L2E * tmp[c];
        sbias[k] = -L2E * s;
    }

    // ---- stage x: 256 tokens * 32B, coalesced; kept in regs for phase 1 ----
    const float* xg = x + ((size_t)b * T_ + blk * TOK_PER_BLOCK) * C_;
    const float4* xp4 = (const float4*)xg;
    float4 pa0 = xp4[tid * 2], pa1 = xp4[tid * 2 + 1];
    float4 pb0 = xp4[(tid + 128) * 2], pb1 = xp4[(tid + 128) * 2 + 1];
    sx[tid * 2] = pa0;  sx[tid * 2 + 1] = pa1;
    sx[(tid + 128) * 2] = pb0;  sx[(tid + 128) * 2 + 1] = pb1;
    __syncthreads();

    // ---- phase 1: per-thread softmax denominators for 2 tokens ----
    {
        float xa[C_]  = {pa0.x, pa0.y, pa0.z, pa0.w, pa1.x, pa1.y, pa1.z, pa1.w};
        float xbv[C_] = {pb0.x, pb0.y, pb0.z, pb0.w, pb1.x, pb1.y, pb1.z, pb1.w};
        float s0a = 0.0f, s0b = 0.0f, s1a = 0.0f, s1b = 0.0f;
#pragma unroll 4
        for (int k = 0; k < K_; k++) {
            const float* w = &scw[k * C_];     // broadcast LDS, conflict-free
            float bias = sbias[k];
            float l0 = bias, l1 = bias;
#pragma unroll
            for (int c = 0; c < C_; c++) {
                l0 = fmaf(w[c], xa[c], l0);
                l1 = fmaf(w[c], xbv[c], l1);
            }
            if (k & 1) { s0b += ex2f(l0); s1b += ex2f(l1); }
            else       { s0a += ex2f(l0); s1a += ex2f(l1); }
        }
        sr[tid]       = rcpf(s0a + s0b);
        sr[tid + 128] = rcpf(s1a + s1b);
    }
    __syncthreads();

    // ---- phase 2: warp-per-64-tokens, lane owns k = lane + 32*i ----
    float cwl[5][C_];
    float nl[5];
#pragma unroll
    for (int i = 0; i < 5; i++) {
        int  k = lane + 32 * i;
        bool v = (k < K_);
        if (v) {
#pragma unroll
            for (int c = 0; c < C_; c++) cwl[i][c] = scw[k * C_ + c];
            nl[i] = sbias[k];
        } else {
#pragma unroll
            for (int c = 0; c < C_; c++) cwl[i][c] = 0.0f;
            nl[i] = __int_as_float(0xff800000);   // -inf -> ex2 -> 0
        }
    }

    float num[5][C_];
    float den[5];
#pragma unroll
    for (int i = 0; i < 5; i++) {
        den[i] = 0.0f;
#pragma unroll
        for (int c = 0; c < C_; c++) num[i][c] = 0.0f;
    }

    float* ab = assign_out + ((size_t)b * T_ + blk * TOK_PER_BLOCK + warp * TOKW) * (size_t)K_;
    const float4* s4 = sx + warp * (TOKW * 2);
    const float*  rr = sr + warp * TOKW;
    const bool v4 = (lane + 128) < K_;

    // software pipeline: token tt's x/r loaded one iteration ahead
    float4 nx0 = s4[0];
    float4 nx1 = s4[1];
    float  nr  = rr[0];

#pragma unroll 4
    for (int tt = 0; tt < TOKW; tt++) {
        float4 x0 = nx0;
        float4 x1 = nx1;
        float  r  = nr;
        if (tt + 1 < TOKW) {                  // compile-time resolved under unroll
            nx0 = s4[2 * tt + 2];
            nx1 = s4[2 * tt + 3];
            nr  = rr[tt + 1];
        }
        float xv[C_] = {x0.x, x0.y, x0.z, x0.w, x1.x, x1.y, x1.z, x1.w};

        float a0, a1, a2, a3, a4;
        {
            float e[5];
#pragma unroll
            for (int i = 0; i < 5; i++) {
                float l = nl[i];
#pragma unroll
                for (int c = 0; c < C_; c++) l = fmaf(cwl[i][c], xv[c], l);
                e[i] = ex2f(l);
            }
            a0 = e[0] * r; a1 = e[1] * r; a2 = e[2] * r; a3 = e[3] * r; a4 = e[4] * r;
        }

        float* ap = ab + (size_t)tt * K_;
        ap[lane]       = a0;          // each a coalesced 128B store
        ap[lane + 32]  = a1;
        ap[lane + 64]  = a2;
        ap[lane + 96]  = a3;
        if (v4) ap[lane + 128] = a4;

        den[0] += a0; den[1] += a1; den[2] += a2; den[3] += a3; den[4] += a4;
        float aa[5] = {a0, a1, a2, a3, a4};
#pragma unroll
        for (int i = 0; i < 5; i++)
#pragma unroll
            for (int c = 0; c < C_; c++) num[i][c] = fmaf(aa[i], xv[c], num[i][c]);
    }

    // Flush partials: 45 REDG per lane (amortized over 64 tokens)
#pragma unroll
    for (int i = 0; i < 5; i++) {
        int k = lane + 32 * i;
        if (k < K_) {
            atomicAdd(&g_den[b * K_ + k], den[i]);
#pragma unroll
            for (int c = 0; c < C_; c++)
                atomicAdd(&g_num[(b * K_ + k) * C_ + c], num[i][c]);
        }
    }
}

// Divide, then self-clean the accumulators for the next call.
// 8 consecutive i share one g_den entry and live in the same warp: the LDG of
// den precedes the lane-0 STG of zero in program order, so no race.
__global__ void finalize_kernel(float* __restrict__ pe) {
    int i = blockIdx.x * blockDim.x + threadIdx.x;
    if (i < B_ * K_ * C_) {
        float d = g_den[i >> 3];   // C_ == 8
        float n = g_num[i];
        pe[i] = n / (d + 1e-8f);
        g_num[i] = 0.0f;
        if ((i & 7) == 0) g_den[i >> 3] = 0.0f;
    }
}

// Keeps the 3-launches cadence so the fixed ncu capture slot profiles the main kernel.
__global__ void pad_kernel() {}

extern "C" void kernel_launch(void* const* d_in, const int* in_sizes, int n_in,
                              void* d_out, int out_size) {
    const float* x    = (const float*)d_in[0];   // [B,T,C]
    const float* cent = (const float*)d_in[1];   // [K,C]
    float* out        = (float*)d_out;
    float* pe_out     = out;                               // [B,K,C] (tuple order)
    float* assign_out = out + (size_t)B_ * K_ * C_;        // [B,T,K]

    softkmeans_kernel<<<GRID_, THREADS_>>>(x, cent, assign_out);
    finalize_kernel<<<(B_ * K_ * C_ + 255) / 256, 256>>>(pe_out);
    pad_kernel<<<1, 32>>>();
}

// round 17
// speedup vs baseline: 1.1800x; 1.0181x over previous
#include <cuda_runtime.h>

// Problem constants
#define B_ 64
#define T_ 4096
#define C_ 8
#define K_ 150
#define TOKW 64                            // tokens per warp
#define WARPS_ 4
#define THREADS_ (WARPS_ * 32)             // 128
#define TOK_PER_BLOCK (WARPS_ * TOKW)      // 256
#define BLOCKS_PER_B (T_ / TOK_PER_BLOCK)  // 16
#define GRID_ (B_ * BLOCKS_PER_B)          // 1024

// Scratch accumulators. __device__ globals are zero-initialized at module load;
// finalize_kernel re-zeroes them after use, so every call sees zeros.
__device__ float g_num[B_ * K_ * C_];   // [B,K,C]
__device__ float g_den[B_ * K_];        // [B,K]

__device__ __forceinline__ float ex2f(float x) {
    float y; asm("ex2.approx.f32 %0, %1;" : "=f"(y) : "f"(x)); return y;
}
__device__ __forceinline__ float rcpf(float x) {
    float y; asm("rcp.approx.f32 %0, %1;" : "=f"(y) : "f"(x)); return y;
}

// Single-phase warp-cooperative kernel, 2 tokens per iteration.
// R12/R13/R16 established: issue% is pinned ~51% for this mix regardless of
// occupancy/ILP/chain length => minimize ISSUED INSTRUCTIONS. Two-phase paid
// +54 instrs/token to avoid 6 shuffle instrs/token — wrong trade. Batch-2
// interleaves the two 5-SHFL butterflies + EX2/dot chains, hiding their
// latency without duplicate work.
//   softmax(-dist) == softmax(2*x.c - |c|^2): |x|^2 cancels across k.
//   exp(l) == 2^(l*log2e): log2e folded into centroid regs -> ONE MUFU.EX2.
// Lane owns k = lane+32*i (i<5); k>=150 masked via bias=-inf (ex2 -> 0).
__global__ void __launch_bounds__(THREADS_, 4)
softkmeans_kernel(const float* __restrict__ x,
                  const float* __restrict__ cent,
                  float* __restrict__ assign_out) {
    __shared__ float4 sx[TOK_PER_BLOCK * 2];   // 8KB x tokens

    const int tid  = threadIdx.x;
    const int warp = tid >> 5;
    const int lane = tid & 31;
    const int b    = blockIdx.x / BLOCKS_PER_B;
    const int blk  = blockIdx.x % BLOCKS_PER_B;
    const float L2E = 1.4426950408889634f;

    // ---- stage x: 256 tokens * 32B per block, coalesced LDG.128 ----
    {
        const float4* xp4 = (const float4*)(x + ((size_t)b * T_ + blk * TOK_PER_BLOCK) * C_);
#pragma unroll
        for (int j = 0; j < 4; j++)
            sx[tid + THREADS_ * j] = xp4[tid + THREADS_ * j];
    }

    // Register-resident centroids, pre-scaled by log2e:
    // cwl = 2*log2e*c ; nl = -log2e*|c|^2 (or -inf for the k>=150 tail)
    float cwl[5][C_];
    float nl[5];
#pragma unroll
    for (int i = 0; i < 5; i++) {
        int  k = lane + 32 * i;
        bool v = (k < K_);
        float s = 0.0f;
#pragma unroll
        for (int c = 0; c < C_; c++) {
            float cv = v ? cent[k * C_ + c] : 0.0f;
            cwl[i][c] = 2.0f * L2E * cv;
            s = fmaf(cv, cv, s);
        }
        nl[i] = v ? (-L2E * s) : __int_as_float(0xff800000);
    }

    float num[5][C_];
    float den[5];
#pragma unroll
    for (int i = 0; i < 5; i++) {
        den[i] = 0.0f;
#pragma unroll
        for (int c = 0; c < C_; c++) num[i][c] = 0.0f;
    }

    __syncthreads();
    const float4* s4 = sx + warp * (TOKW * 2);
    const bool v4 = (lane + 128) < K_;
    // 32-bit addressing: total assignment elements = 39.3M < 2^31
    const int abase = ((b * T_ + blk * TOK_PER_BLOCK + warp * TOKW)) * K_;

    for (int tt = 0; tt < TOKW; tt += 2) {
        // two tokens' x via broadcast LDS.128 (conflict-free)
        float4 xa0 = s4[2 * tt],     xa1 = s4[2 * tt + 1];
        float4 xb0 = s4[2 * tt + 2], xb1 = s4[2 * tt + 3];
        float xvA[C_] = {xa0.x, xa0.y, xa0.z, xa0.w, xa1.x, xa1.y, xa1.z, xa1.w};
        float xvB[C_] = {xb0.x, xb0.y, xb0.z, xb0.w, xb1.x, xb1.y, xb1.z, xb1.w};

        // logits -> EX2, two tokens interleaved (independent chains)
        float eA[5], eB[5];
#pragma unroll
        for (int i = 0; i < 5; i++) {
            float lA = nl[i], lB = nl[i];
#pragma unroll
            for (int c = 0; c < C_; c++) {
                lA = fmaf(cwl[i][c], xvA[c], lA);
                lB = fmaf(cwl[i][c], xvB[c], lB);
            }
            eA[i] = ex2f(lA);
            eB[i] = ex2f(lB);
        }

        float sA = ((eA[0] + eA[1]) + (eA[2] + eA[3])) + eA[4];
        float sB = ((eB[0] + eB[1]) + (eB[2] + eB[3])) + eB[4];
        // two interleaved butterflies: 26-cyc SHFL latencies overlap
#pragma unroll
        for (int off = 16; off; off >>= 1) {
            sA += __shfl_xor_sync(0xffffffffu, sA, off);
            sB += __shfl_xor_sync(0xffffffffu, sB, off);
        }
        float rA = rcpf(sA);
        float rB = rcpf(sB);

        float aA[5], aB[5];
#pragma unroll
        for (int i = 0; i < 5; i++) { aA[i] = eA[i] * rA; aB[i] = eB[i] * rB; }

        float* apA = assign_out + (abase + tt * K_);
        float* apB = apA + K_;
        apA[lane]       = aA[0];      // coalesced 128B stores
        apA[lane + 32]  = aA[1];
        apA[lane + 64]  = aA[2];
        apA[lane + 96]  = aA[3];
        if (v4) apA[lane + 128] = aA[4];
        apB[lane]       = aB[0];
        apB[lane + 32]  = aB[1];
        apB[lane + 64]  = aB[2];
        apB[lane + 96]  = aB[3];
        if (v4) apB[lane + 128] = aB[4];

#pragma unroll
        for (int i = 0; i < 5; i++) {
            den[i] += aA[i] + aB[i];
#pragma unroll
            for (int c = 0; c < C_; c++) {
                num[i][c] = fmaf(aA[i], xvA[c], num[i][c]);
                num[i][c] = fmaf(aB[i], xvB[c], num[i][c]);
            }
        }
    }

    // Flush partials: 45 REDG per lane (amortized over 64 tokens)
#pragma unroll
    for (int i = 0; i < 5; i++) {
        int k = lane + 32 * i;
        if (k < K_) {
            atomicAdd(&g_den[b * K_ + k], den[i]);
#pragma unroll
            for (int c = 0; c < C_; c++)
                atomicAdd(&g_num[(b * K_ + k) * C_ + c], num[i][c]);
        }
    }
}

// Divide, then self-clean the accumulators for the next call.
// 8 consecutive i share one g_den entry and live in the same warp: the LDG of
// den precedes the lane-0 STG of zero in program order, so no race.
__global__ void finalize_kernel(float* __restrict__ pe) {
    int i = blockIdx.x * blockDim.x + threadIdx.x;
    if (i < B_ * K_ * C_) {
        float d = g_den[i >> 3];   // C_ == 8
        float n = g_num[i];
        pe[i] = n / (d + 1e-8f);
        g_num[i] = 0.0f;
        if ((i & 7) == 0) g_den[i >> 3] = 0.0f;
    }
}

// Keeps the 3-launches cadence so the fixed ncu capture slot profiles the main kernel.
__global__ void pad_kernel() {}

extern "C" void kernel_launch(void* const* d_in, const int* in_sizes, int n_in,
                              void* d_out, int out_size) {
    const float* x    = (const float*)d_in[0];   // [B,T,C]
    const float* cent = (const float*)d_in[1];   // [K,C]
    float* out        = (float*)d_out;
    float* pe_out     = out;                               // [B,K,C] (tuple order)
    float* assign_out = out + (size_t)B_ * K_ * C_;        // [B,T,K]

    softkmeans_kernel<<<GRID_, THREADS_>>>(x, cent, assign_out);
    finalize_kernel<<<(B_ * K_ * C_ + 255) / 256, 256>>>(pe_out);
    pad_kernel<<<1, 32>>>();
}